// round 8
// baseline (speedup 1.0000x reference)
#include <cuda_runtime.h>
#include <cuda_bf16.h>
#include <math_constants.h>

#define CC 64
#define HH 100
#define WW 252
#define KK 5
#define LL 5
#define BB 2
#define CPT 8
#define MAX_IMGS (LL * KK)
#define TPB 256

__global__ __launch_bounds__(TPB, 6)
void raindrop_fuse_kernel(const float* __restrict__ x,
                          const float* __restrict__ ptm,
                          const int*   __restrict__ record_len,
                          float*       __restrict__ out) {
    constexpr int HW = HH * WW;
    constexpr float S = 1.6f;  // DOWNSAMPLE * VOXEL

    const int b   = blockIdx.z;
    const int cg  = blockIdx.y;
    const int pix = blockIdx.x * TPB + threadIdx.x;

    __shared__ float th[MAX_IMGS][6];

    const int N       = record_len[b];
    const int numImgs = N * KK;
    const int start   = (b == 0) ? 0 : record_len[0] * KK;

    // theta' folds the reference `mult` scaling AND the grid->pixel transform.
    if (threadIdx.x < numImgs * 6) {
        const int idx = threadIdx.x;
        const int n = idx / 6, e = idx % 6;
        const int l = n / KK, k = n % KK;
        const int i = e / 3, j = e % 3;
        const int jj = (j == 2) ? 3 : j;
        const float mult[2][3] = {
            {1.0f, (float)HH / (float)WW, 2.0f / (S * WW)},
            {(float)WW / (float)HH, 1.0f, 2.0f / (S * HH)}
        };
        const float halfdim = (i == 0) ? ((float)WW * 0.5f) : ((float)HH * 0.5f);
        float v = ptm[((((b * LL) + l) * KK + k) * 4 + i) * 4 + jj] * mult[i][j];
        v *= halfdim;
        if (j == 2) v += halfdim - 0.5f;
        th[n][e] = v;
    }
    __syncthreads();

    if (pix >= HW) return;

    const int h = pix / WW;
    const int w = pix - h * WW;
    const float gx = (2.0f * (float)w + 1.0f) * (1.0f / (float)WW) - 1.0f;
    const float gy = (2.0f * (float)h + 1.0f) * (1.0f / (float)HH) - 1.0f;

    float acc[CPT];
#pragma unroll
    for (int c = 0; c < CPT; c++) acc[c] = -CUDART_INF_F;
    float oobVal = -CUDART_INF_F;

    // uniform (per-block) base pointer; per-thread addressing is 32-bit offsets
    const float* pimg = x + (size_t)(start * CC + cg * CPT) * (size_t)HW;

    for (int n = 0; n < numImgs; n++, pimg += (size_t)CC * HW) {
        const float px = th[n][0] * gx + th[n][1] * gy + th[n][2];
        const float py = th[n][3] * gx + th[n][4] * gy + th[n][5];
        const int ix0 = __float2int_rd(px);
        const int iy0 = __float2int_rd(py);
        const float wx = px - (float)ix0;
        const float wy = py - (float)iy0;
        const int ix1 = ix0 + 1;
        const int iy1 = iy0 + 1;

        const bool vx0 = (ix0 >= 0) & (ix0 < WW);
        const bool vx1 = (ix1 >= 0) & (ix1 < WW);
        const bool vy0 = (iy0 >= 0) & (iy0 < HH);
        const bool vy1 = (iy1 >= 0) & (iy1 < HH);

        if (!((vx0 | vx1) & (vy0 | vy1))) {
            oobVal = 0.0f;          // zeros padding joins the max
            continue;
        }

        const float w00 = (1.0f - wx) * (1.0f - wy) * (float)(vx0 && vy0);
        const float w01 = wx * (1.0f - wy) * (float)(vx1 && vy0);
        const float w10 = (1.0f - wx) * wy * (float)(vx0 && vy1);
        const float w11 = wx * wy * (float)(vx1 && vy1);

        const int ix0c = min(max(ix0, 0), WW - 1);
        const int ix1c = min(max(ix1, 0), WW - 1);
        const int iy0c = min(max(iy0, 0), HH - 1);
        const int iy1c = min(max(iy1, 0), HH - 1);

        const int o00 = iy0c * WW + ix0c;
        const int o01 = o00 + (ix1c - ix0c);
        const int o10 = iy1c * WW + ix0c;
        const int o11 = o10 + (ix1c - ix0c);

        // two half-batches of 4 channels: 16 loads in flight each;
        // channel offsets are compile-time immediates (c*HW).
#pragma unroll
        for (int half = 0; half < 2; half++) {
            const int cbase = half * 4;
            const float* p = pimg + cbase * HW;
            float v00[4], v01[4], v10[4], v11[4];
#pragma unroll
            for (int c = 0; c < 4; c++) {
                v00[c] = __ldg(p + c * HW + o00);
                v01[c] = __ldg(p + c * HW + o01);
                v10[c] = __ldg(p + c * HW + o10);
                v11[c] = __ldg(p + c * HW + o11);
            }
#pragma unroll
            for (int c = 0; c < 4; c++) {
                const float val = w00 * v00[c] + w01 * v01[c]
                                + w10 * v10[c] + w11 * v11[c];
                acc[cbase + c] = fmaxf(acc[cbase + c], val);
            }
        }
    }

    float* ob = out + ((size_t)(b * CC + cg * CPT)) * HW + pix;
#pragma unroll
    for (int c = 0; c < CPT; c++) ob[c * HW] = fmaxf(acc[c], oobVal);
}

extern "C" void kernel_launch(void* const* d_in, const int* in_sizes, int n_in,
                              void* d_out, int out_size) {
    const float* x   = (const float*)d_in[0];
    // d_in[1] = rm (unused), d_in[3] = time_diffs (unused)
    const float* ptm = (const float*)d_in[2];
    const int*   rl  = (const int*)d_in[4];
    float* out = (float*)d_out;

    constexpr int HW = HH * WW;
    dim3 block(TPB);
    dim3 grid((HW + TPB - 1) / TPB, CC / CPT, BB);
    raindrop_fuse_kernel<<<grid, block>>>(x, ptm, rl, out);
}

// round 10
// speedup vs baseline: 1.2459x; 1.2459x over previous
#include <cuda_runtime.h>
#include <cuda_bf16.h>
#include <math_constants.h>

#define CC 64
#define HH 100
#define WW 252
#define KK 5
#define LL 5
#define BB 2
#define CPT 8
#define MAX_IMGS (LL * KK)
#define TPB 128
#define HWB (HH * WW * 4)          // channel stride in bytes

__global__ __launch_bounds__(TPB, 10)
void raindrop_fuse_kernel(const float* __restrict__ x,
                          const float* __restrict__ ptm,
                          const int*   __restrict__ record_len,
                          float*       __restrict__ out) {
    constexpr int HW = HH * WW;
    constexpr float S = 1.6f;  // DOWNSAMPLE * VOXEL

    const int b   = blockIdx.z;
    const int cg  = blockIdx.y;
    const int pix = blockIdx.x * TPB + threadIdx.x;

    __shared__ float th[MAX_IMGS][6];

    const int N       = record_len[b];
    const int numImgs = N * KK;
    const int start   = (b == 0) ? 0 : record_len[0] * KK;

    // theta' folds the reference `mult` scaling AND the grid->pixel transform.
    // NOTE: numImgs*6 can exceed TPB (150 > 128) -> MUST be a strided loop.
    for (int idx = threadIdx.x; idx < numImgs * 6; idx += TPB) {
        const int n = idx / 6, e = idx % 6;
        const int l = n / KK, k = n % KK;
        const int i = e / 3, j = e % 3;
        const int jj = (j == 2) ? 3 : j;
        const float mult[2][3] = {
            {1.0f, (float)HH / (float)WW, 2.0f / (S * WW)},
            {(float)WW / (float)HH, 1.0f, 2.0f / (S * HH)}
        };
        const float halfdim = (i == 0) ? ((float)WW * 0.5f) : ((float)HH * 0.5f);
        float v = ptm[((((b * LL) + l) * KK + k) * 4 + i) * 4 + jj] * mult[i][j];
        v *= halfdim;
        if (j == 2) v += halfdim - 0.5f;
        th[n][e] = v;
    }
    __syncthreads();

    if (pix >= HW) return;

    const int h = pix / WW;
    const int w = pix - h * WW;
    const float gx = (2.0f * (float)w + 1.0f) * (1.0f / (float)WW) - 1.0f;
    const float gy = (2.0f * (float)h + 1.0f) * (1.0f / (float)HH) - 1.0f;

    float acc[CPT];
#pragma unroll
    for (int c = 0; c < CPT; c++) acc[c] = -CUDART_INF_F;
    float oobVal = -CUDART_INF_F;

    // image base (bytes), channel-group offset folded in
    const char* pimg = (const char*)x
                     + (size_t)start * CC * (size_t)HWB
                     + (unsigned)(cg * CPT) * (unsigned)HWB;

    for (int n = 0; n < numImgs; n++, pimg += (size_t)CC * HWB) {
        const float px = th[n][0] * gx + th[n][1] * gy + th[n][2];
        const float py = th[n][3] * gx + th[n][4] * gy + th[n][5];
        const float fx0 = floorf(px);
        const float fy0 = floorf(py);
        const float wx = px - fx0;
        const float wy = py - fy0;
        const int ix0 = (int)fx0;
        const int iy0 = (int)fy0;
        const int ix1 = ix0 + 1;
        const int iy1 = iy0 + 1;

        const bool vx0 = (ix0 >= 0) & (ix0 < WW);
        const bool vx1 = (ix1 >= 0) & (ix1 < WW);
        const bool vy0 = (iy0 >= 0) & (iy0 < HH);
        const bool vy1 = (iy1 >= 0) & (iy1 < HH);

        if (!((vx0 | vx1) & (vy0 | vy1))) {
            oobVal = 0.0f;          // zeros padding participates in the max
            continue;
        }

        const float w00 = (1.0f - wx) * (1.0f - wy) * (float)(vx0 && vy0);
        const float w01 = wx * (1.0f - wy) * (float)(vx1 && vy0);
        const float w10 = (1.0f - wx) * wy * (float)(vx0 && vy1);
        const float w11 = wx * wy * (float)(vx1 && vy1);

        const int ix0c = min(max(ix0, 0), WW - 1);
        const int ix1c = min(max(ix1, 0), WW - 1);
        const int iy0c = min(max(iy0, 0), HH - 1);
        const int iy1c = min(max(iy1, 0), HH - 1);

        // 4 byte-base addresses for this image; channel loop uses imm offsets
        const char* a00 = pimg + (unsigned)((iy0c * WW + ix0c) * 4);
        const char* a01 = pimg + (unsigned)((iy0c * WW + ix1c) * 4);
        const char* a10 = pimg + (unsigned)((iy1c * WW + ix0c) * 4);
        const char* a11 = pimg + (unsigned)((iy1c * WW + ix1c) * 4);

        // two half-batches of 4 channels: 16 loads in flight each
#pragma unroll
        for (int half = 0; half < 2; half++) {
            const int cbase = half * 4;
            float v00[4], v01[4], v10[4], v11[4];
#pragma unroll
            for (int c = 0; c < 4; c++) {
                const int cc = cbase + c;
                v00[c] = __ldg((const float*)(a00 + cc * HWB));
                v01[c] = __ldg((const float*)(a01 + cc * HWB));
                v10[c] = __ldg((const float*)(a10 + cc * HWB));
                v11[c] = __ldg((const float*)(a11 + cc * HWB));
            }
#pragma unroll
            for (int c = 0; c < 4; c++) {
                const float val = w00 * v00[c] + w01 * v01[c]
                                + w10 * v10[c] + w11 * v11[c];
                acc[cbase + c] = fmaxf(acc[cbase + c], val);
            }
        }
    }

    float* ob = out + ((size_t)(b * CC + cg * CPT)) * HW + pix;
#pragma unroll
    for (int c = 0; c < CPT; c++) ob[c * HW] = fmaxf(acc[c], oobVal);
}

extern "C" void kernel_launch(void* const* d_in, const int* in_sizes, int n_in,
                              void* d_out, int out_size) {
    const float* x   = (const float*)d_in[0];
    // d_in[1] = rm (unused), d_in[3] = time_diffs (unused)
    const float* ptm = (const float*)d_in[2];
    const int*   rl  = (const int*)d_in[4];
    float* out = (float*)d_out;

    constexpr int HW = HH * WW;
    dim3 block(TPB);
    dim3 grid((HW + TPB - 1) / TPB, CC / CPT, BB);
    raindrop_fuse_kernel<<<grid, block>>>(x, ptm, rl, out);
}